// round 1
// baseline (speedup 1.0000x reference)
#include <cuda_runtime.h>
#include <cstdint>

#define D_IN  128
#define D_HID 512
#define D_OUT 256
#define NMAX  100000
#define EMAX  1600000
#define MPAD  100096   // ceil(100000/128)*128

// ---------------- scratch (device globals; no allocation allowed) ----------
__device__ int   g_deg[NMAX + 1];
__device__ int   g_off[NMAX + 1];
__device__ int   g_cur[NMAX];
__device__ int   g_bsum[128];
__device__ int   g_csrc[EMAX];
__device__ float g_cw[EMAX];
__device__ float g_hin[(size_t)MPAD * D_IN];
__device__ float g_h1 [(size_t)MPAD * D_HID];
__device__ float g_sum[D_HID], g_sq[D_HID];
__device__ float g_scale[D_HID], g_shift[D_HID];

// ---------------- init ------------------------------------------------------
__global__ void zero_kernel(int n1) {
    int i = blockIdx.x * blockDim.x + threadIdx.x;
    if (i < n1) g_deg[i] = 0;
    if (i < D_HID) { g_sum[i] = 0.f; g_sq[i] = 0.f; }
}

// ---------------- CSR build --------------------------------------------------
__global__ void hist_kernel(const int* __restrict__ edst, int E) {
    int i = blockIdx.x * blockDim.x + threadIdx.x;
    if (i < E) atomicAdd(&g_deg[edst[i]], 1);
}

__global__ void scan1_kernel(int n) {
    __shared__ int sh[1024];
    int tid = threadIdx.x;
    int i = blockIdx.x * 1024 + tid;
    int v = (i < n) ? g_deg[i] : 0;
    sh[tid] = v;
    __syncthreads();
    for (int o = 1; o < 1024; o <<= 1) {
        int t = (tid >= o) ? sh[tid - o] : 0;
        __syncthreads();
        sh[tid] += t;
        __syncthreads();
    }
    if (i < n) g_off[i] = sh[tid] - v;            // exclusive
    if (tid == 1023) g_bsum[blockIdx.x] = sh[1023];
}

__global__ void scan2_kernel(int nb) {
    if (threadIdx.x == 0) {
        int acc = 0;
        for (int i = 0; i < nb; i++) { int t = g_bsum[i]; g_bsum[i] = acc; acc += t; }
    }
}

__global__ void scan3_kernel(int n, int N) {
    int i = blockIdx.x * 1024 + threadIdx.x;
    if (i < n) {
        int v = g_off[i] + g_bsum[blockIdx.x];
        g_off[i] = v;
        if (i < N) g_cur[i] = v;
    }
}

__global__ void scatter_kernel(const int* __restrict__ esrc,
                               const int* __restrict__ edst,
                               const float* __restrict__ ew, int E) {
    int i = blockIdx.x * blockDim.x + threadIdx.x;
    if (i < E) {
        int d = edst[i];
        int p = atomicAdd(&g_cur[d], 1);
        g_csrc[p] = esrc[i];
        g_cw[p]   = ew[i];
    }
}

// ---------------- SpMM: warp per dst row; h_in = (1+eps)x + agg --------------
__global__ void spmm_kernel(const float* __restrict__ x, int N, int Mpad) {
    int warp = (blockIdx.x * blockDim.x + threadIdx.x) >> 5;  // = dst row
    int lane = threadIdx.x & 31;
    if (warp >= Mpad) return;
    float4* outp = (float4*)(g_hin + (size_t)warp * D_IN);
    if (warp >= N) { outp[lane] = make_float4(0.f, 0.f, 0.f, 0.f); return; }
    float ax = 0.f, ay = 0.f, az = 0.f, aw = 0.f;
    int e0 = g_off[warp], e1 = g_off[warp + 1];
    for (int e = e0; e < e1; e++) {
        int s = g_csrc[e];
        float w = g_cw[e];
        float4 v = ((const float4*)(x + (size_t)s * D_IN))[lane];
        ax = fmaf(w, v.x, ax);
        ay = fmaf(w, v.y, ay);
        az = fmaf(w, v.z, az);
        aw = fmaf(w, v.w, aw);
    }
    float4 xv = ((const float4*)(x + (size_t)warp * D_IN))[lane];
    const float c = 1.0f + 1e-9f;
    outp[lane] = make_float4(fmaf(c, xv.x, ax), fmaf(c, xv.y, ay),
                             fmaf(c, xv.z, az), fmaf(c, xv.w, aw));
}

// ---------------- SGEMM 128x128x8, 256 thr, 8x8/thread ----------------------
// FUSE_BN: A element -> relu(a*scale[k]+shift[k]) on load
// STATS:   accumulate per-column sum/sumsq of C (rows < M) into g_sum/g_sq
template <bool FUSE_BN, bool STATS>
__device__ __forceinline__ void sgemm_body(
    const float* __restrict__ A, const float* __restrict__ B,
    float* __restrict__ C, const float* __restrict__ bias,
    int M, int Mstore, int K, int ncols,
    const float* __restrict__ scale, const float* __restrict__ shift)
{
    __shared__ float As[8][132];
    __shared__ float Bs[8][128];
    __shared__ float s_sum[128];
    __shared__ float s_sq[128];

    int tid = threadIdx.x;
    int tx = tid & 15, ty = tid >> 4;
    int brow = blockIdx.y * 128;
    int bcol = blockIdx.x * 128;

    int a_row = tid >> 1;             // 0..127
    int a_k4  = (tid & 1) * 4;        // 0 or 4
    int b_k   = tid >> 5;             // 0..7
    int b_c4  = (tid & 31) * 4;       // 0..124

    const float* Aptr = A + (size_t)(brow + a_row) * K + a_k4;
    const float* Bptr = B + (size_t)b_k * ncols + bcol + b_c4;

    float acc[8][8];
#pragma unroll
    for (int i = 0; i < 8; i++)
#pragma unroll
        for (int j = 0; j < 8; j++) acc[i][j] = 0.f;

    for (int kk = 0; kk < K; kk += 8) {
        float4 av = *(const float4*)(Aptr + kk);
        if (FUSE_BN) {
            float4 sc = *(const float4*)(scale + kk + a_k4);
            float4 sh = *(const float4*)(shift + kk + a_k4);
            av.x = fmaxf(fmaf(av.x, sc.x, sh.x), 0.f);
            av.y = fmaxf(fmaf(av.y, sc.y, sh.y), 0.f);
            av.z = fmaxf(fmaf(av.z, sc.z, sh.z), 0.f);
            av.w = fmaxf(fmaf(av.w, sc.w, sh.w), 0.f);
        }
        float4 bv = *(const float4*)(Bptr + (size_t)kk * ncols);
        As[a_k4 + 0][a_row] = av.x;
        As[a_k4 + 1][a_row] = av.y;
        As[a_k4 + 2][a_row] = av.z;
        As[a_k4 + 3][a_row] = av.w;
        *(float4*)&Bs[b_k][b_c4] = bv;
        __syncthreads();
#pragma unroll
        for (int k = 0; k < 8; k++) {
            float ar[8], br[8];
            *(float4*)&ar[0] = *(const float4*)&As[k][ty * 8];
            *(float4*)&ar[4] = *(const float4*)&As[k][ty * 8 + 4];
            *(float4*)&br[0] = *(const float4*)&Bs[k][tx * 8];
            *(float4*)&br[4] = *(const float4*)&Bs[k][tx * 8 + 4];
#pragma unroll
            for (int i = 0; i < 8; i++)
#pragma unroll
                for (int j = 0; j < 8; j++)
                    acc[i][j] = fmaf(ar[i], br[j], acc[i][j]);
        }
        __syncthreads();
    }

    float bvec[8];
#pragma unroll
    for (int j = 0; j < 8; j++) bvec[j] = bias[bcol + tx * 8 + j];

    if (STATS) {
        if (tid < 128) { s_sum[tid] = 0.f; s_sq[tid] = 0.f; }
        __syncthreads();
    }

    float ls[8], lq[8];
#pragma unroll
    for (int j = 0; j < 8; j++) { ls[j] = 0.f; lq[j] = 0.f; }

#pragma unroll
    for (int i = 0; i < 8; i++) {
        int row = brow + ty * 8 + i;
        float vals[8];
#pragma unroll
        for (int j = 0; j < 8; j++) vals[j] = acc[i][j] + bvec[j];
        if (row < Mstore) {
            float* crow = C + (size_t)row * ncols + bcol + tx * 8;
            *(float4*)(crow)     = *(float4*)&vals[0];
            *(float4*)(crow + 4) = *(float4*)&vals[4];
        }
        if (STATS && row < M) {
#pragma unroll
            for (int j = 0; j < 8; j++) {
                ls[j] += vals[j];
                lq[j] = fmaf(vals[j], vals[j], lq[j]);
            }
        }
    }

    if (STATS) {
#pragma unroll
        for (int j = 0; j < 8; j++) {
            atomicAdd(&s_sum[tx * 8 + j], ls[j]);
            atomicAdd(&s_sq[tx * 8 + j], lq[j]);
        }
        __syncthreads();
        if (tid < 128) {
            atomicAdd(&g_sum[bcol + tid], s_sum[tid]);
            atomicAdd(&g_sq[bcol + tid],  s_sq[tid]);
        }
    }
}

__global__ __launch_bounds__(256)
void gemm1_kernel(const float* __restrict__ B, const float* __restrict__ bias, int M) {
    sgemm_body<false, true>(g_hin, B, g_h1, bias, M, MPAD, D_IN, D_HID,
                            nullptr, nullptr);
}

__global__ __launch_bounds__(256)
void gemm2_kernel(const float* __restrict__ B, const float* __restrict__ bias,
                  float* __restrict__ C, int M) {
    sgemm_body<true, false>(g_h1, B, C, bias, M, M, D_HID, D_OUT,
                            g_scale, g_shift);
}

// ---------------- BN finalize: scale/shift from sums ------------------------
__global__ void finalize_kernel(const float* __restrict__ gamma,
                                const float* __restrict__ beta, int M) {
    int c = blockIdx.x * blockDim.x + threadIdx.x;
    if (c < D_HID) {
        float inv = 1.0f / (float)M;
        float m   = g_sum[c] * inv;
        float var = fmaxf(g_sq[c] * inv - m * m, 0.f);
        float r   = rsqrtf(var + 1e-5f);
        float sc  = r * gamma[c];
        g_scale[c] = sc;
        g_shift[c] = fmaf(-m, sc, beta[c]);
    }
}

// ---------------- launch -----------------------------------------------------
extern "C" void kernel_launch(void* const* d_in, const int* in_sizes, int n_in,
                              void* d_out, int out_size) {
    const float* x     = (const float*)d_in[0];
    const int*   esrc  = (const int*)  d_in[1];
    const int*   edst  = (const int*)  d_in[2];
    const float* ew    = (const float*)d_in[3];
    const float* w1    = (const float*)d_in[4];
    const float* b1    = (const float*)d_in[5];
    const float* gamma = (const float*)d_in[6];
    const float* beta  = (const float*)d_in[7];
    const float* w2    = (const float*)d_in[8];
    const float* b2    = (const float*)d_in[9];
    float* out = (float*)d_out;

    int N = in_sizes[0] / D_IN;
    int E = in_sizes[1];
    if (N > NMAX) N = NMAX;
    if (E > EMAX) E = EMAX;

    int n1 = N + 1;
    int nb = (n1 + 1023) / 1024;

    // init
    zero_kernel<<<(n1 + 1023) / 1024, 1024>>>(n1);
    // CSR build
    hist_kernel<<<(E + 255) / 256, 256>>>(edst, E);
    scan1_kernel<<<nb, 1024>>>(n1);
    scan2_kernel<<<1, 32>>>(nb);
    scan3_kernel<<<nb, 1024>>>(n1, N);
    scatter_kernel<<<(E + 255) / 256, 256>>>(esrc, edst, ew, E);
    // SpMM + (1+eps)x
    {
        int warps = MPAD;                 // 1 warp per row (incl. zero pad rows)
        int blocks = (warps * 32 + 255) / 256;
        spmm_kernel<<<blocks, 256>>>(x, N, MPAD);
    }
    // GEMM1 (+bias, +BN column stats)
    {
        dim3 grid(D_HID / 128, MPAD / 128);
        gemm1_kernel<<<grid, 256>>>(w1, b1, N);
    }
    // BN scale/shift
    finalize_kernel<<<1, 512>>>(gamma, beta, N);
    // GEMM2 with fused BN+ReLU on A (+bias), store to d_out
    {
        dim3 grid(D_OUT / 128, MPAD / 128);
        gemm2_kernel<<<grid, 256>>>(w2, b2, out, N);
    }
}

// round 2
// speedup vs baseline: 1.9767x; 1.9767x over previous
#include <cuda_runtime.h>
#include <cstdint>

#define D_IN  128
#define D_HID 512
#define D_OUT 256
#define NMAX  100000
#define EMAX  1600000
#define MPAD  100096   // ceil(100000/128)*128

// ---------------- scratch (device globals; no allocation allowed) ----------
__device__ int   g_deg[NMAX + 1];
__device__ int   g_off[NMAX + 1];
__device__ int   g_cur[NMAX];
__device__ int   g_bsum[128];
__device__ int   g_csrc[EMAX];
__device__ float g_cw[EMAX];
__device__ float g_hin[(size_t)MPAD * D_IN];
__device__ float g_h1 [(size_t)MPAD * D_HID];
__device__ float g_sum[D_HID], g_sq[D_HID];
__device__ float g_scale[D_HID], g_shift[D_HID];

// ---------------- init ------------------------------------------------------
__global__ void zero_kernel(int n1) {
    int i = blockIdx.x * blockDim.x + threadIdx.x;
    if (i < n1) g_deg[i] = 0;
    if (i < D_HID) { g_sum[i] = 0.f; g_sq[i] = 0.f; }
}

// ---------------- CSR build --------------------------------------------------
__global__ void hist_kernel(const int* __restrict__ edst, int E) {
    int i = blockIdx.x * blockDim.x + threadIdx.x;
    if (i < E) atomicAdd(&g_deg[edst[i]], 1);
}

__global__ void scan1_kernel(int n) {
    __shared__ int sh[1024];
    int tid = threadIdx.x;
    int i = blockIdx.x * 1024 + tid;
    int v = (i < n) ? g_deg[i] : 0;
    sh[tid] = v;
    __syncthreads();
    for (int o = 1; o < 1024; o <<= 1) {
        int t = (tid >= o) ? sh[tid - o] : 0;
        __syncthreads();
        sh[tid] += t;
        __syncthreads();
    }
    if (i < n) g_off[i] = sh[tid] - v;            // exclusive
    if (tid == 1023) g_bsum[blockIdx.x] = sh[1023];
}

__global__ void scan2_kernel(int nb) {   // nb <= 128; parallel exclusive scan
    __shared__ int sh[128];
    int t = threadIdx.x;
    int v = (t < nb) ? g_bsum[t] : 0;
    sh[t] = v;
    __syncthreads();
    for (int o = 1; o < 128; o <<= 1) {
        int u = (t >= o) ? sh[t - o] : 0;
        __syncthreads();
        sh[t] += u;
        __syncthreads();
    }
    if (t < nb) g_bsum[t] = sh[t] - v;
}

__global__ void scan3_kernel(int n, int N) {
    int i = blockIdx.x * 1024 + threadIdx.x;
    if (i < n) {
        int v = g_off[i] + g_bsum[blockIdx.x];
        g_off[i] = v;
        if (i < N) g_cur[i] = v;
    }
}

__global__ void scatter_kernel(const int* __restrict__ esrc,
                               const int* __restrict__ edst,
                               const float* __restrict__ ew, int E) {
    int i = blockIdx.x * blockDim.x + threadIdx.x;
    if (i < E) {
        int d = edst[i];
        int p = atomicAdd(&g_cur[d], 1);
        g_csrc[p] = esrc[i];
        g_cw[p]   = ew[i];
    }
}

// ---------------- SpMM: warp per dst row; h_in = (1+eps)x + agg --------------
__global__ void spmm_kernel(const float* __restrict__ x, int N, int Mpad) {
    int warp = (blockIdx.x * blockDim.x + threadIdx.x) >> 5;  // = dst row
    int lane = threadIdx.x & 31;
    if (warp >= Mpad) return;
    float4* outp = (float4*)(g_hin + (size_t)warp * D_IN);
    if (warp >= N) { outp[lane] = make_float4(0.f, 0.f, 0.f, 0.f); return; }
    float ax = 0.f, ay = 0.f, az = 0.f, aw = 0.f;
    int e0 = g_off[warp], e1 = g_off[warp + 1];
    for (int e = e0; e < e1; e++) {
        int s = g_csrc[e];
        float w = g_cw[e];
        float4 v = ((const float4*)(x + (size_t)s * D_IN))[lane];
        ax = fmaf(w, v.x, ax);
        ay = fmaf(w, v.y, ay);
        az = fmaf(w, v.z, az);
        aw = fmaf(w, v.w, aw);
    }
    float4 xv = ((const float4*)(x + (size_t)warp * D_IN))[lane];
    const float c = 1.0f + 1e-9f;
    outp[lane] = make_float4(fmaf(c, xv.x, ax), fmaf(c, xv.y, ay),
                             fmaf(c, xv.z, az), fmaf(c, xv.w, aw));
}

// ---------------- TF32 tensor-core helpers ----------------------------------
__device__ __forceinline__ uint32_t f2tf32(float f) {
    uint32_t u;
    asm("cvt.rna.tf32.f32 %0, %1;" : "=r"(u) : "f"(f));
    return u;
}

__device__ __forceinline__ void mma_tf32(float d[4], const uint32_t a[4],
                                         const uint32_t b[2]) {
    asm volatile(
        "mma.sync.aligned.m16n8k8.row.col.f32.tf32.tf32.f32 "
        "{%0,%1,%2,%3},{%4,%5,%6,%7},{%8,%9},{%0,%1,%2,%3};\n"
        : "+f"(d[0]), "+f"(d[1]), "+f"(d[2]), "+f"(d[3])
        : "r"(a[0]), "r"(a[1]), "r"(a[2]), "r"(a[3]),
          "r"(b[0]), "r"(b[1]));
}

// ---------------- TF32 GEMM: 128x128 CTA tile, BK=16, 8 warps (64x32 each) --
// FUSE_BN: A element -> relu(a*scale[k]+shift[k]) applied on global load
// STATS:   accumulate per-column sum/sumsq of C (rows < M) into g_sum/g_sq
template <bool FUSE_BN, bool STATS>
__device__ __forceinline__ void mma_gemm(
    const float* __restrict__ A, const float* __restrict__ B,
    float* __restrict__ C, const float* __restrict__ bias,
    int M, int Mstore, int K, int ncols,
    const float* __restrict__ scale, const float* __restrict__ shift)
{
    __shared__ uint32_t As[128][20];   // [m][k], pad 20 -> conflict-free frags
    __shared__ uint32_t Bs[16][136];   // [k][n], pad 136 -> conflict-free frags
    __shared__ float s_sum[128];
    __shared__ float s_sq[128];

    const int tid  = threadIdx.x;
    const int lane = tid & 31;
    const int wid  = tid >> 5;
    const int wm   = wid & 1;          // warp row (2 x 64)
    const int wn   = wid >> 1;         // warp col (4 x 32)
    const int g    = lane >> 2;        // group id 0..7
    const int tig  = lane & 3;         // thread in group
    const int brow = blockIdx.y * 128;
    const int bcol = blockIdx.x * 128;

    // A global-load indexing: 128 rows x 16 k = 512 float4, 2 per thread
    const int a_row = tid >> 2;              // 0..63 (+64 for second)
    const int a_k4  = (tid & 3) << 2;        // 0,4,8,12
    // B global-load indexing: 16 k x 128 n = 512 float4, 2 per thread
    const int b_k   = tid >> 5;              // 0..7 (+8 for second)
    const int b_c4  = (tid & 31) << 2;       // 0..124

    const float* Abase = A + (size_t)(brow + a_row) * K + a_k4;
    const float* Bbase = B + (size_t)b_k * ncols + bcol + b_c4;
    const size_t AstepRow = (size_t)64 * K;
    const size_t BstepK   = (size_t)8 * ncols;

    float acc[4][4][4];
#pragma unroll
    for (int mf = 0; mf < 4; mf++)
#pragma unroll
        for (int nf = 0; nf < 4; nf++)
#pragma unroll
            for (int q = 0; q < 4; q++) acc[mf][nf][q] = 0.f;

    float4 pa0, pa1, pb0, pb1;

    auto loadA = [&](int kk, float4& v0, float4& v1) {
        v0 = *(const float4*)(Abase + kk);
        v1 = *(const float4*)(Abase + AstepRow + kk);
        if (FUSE_BN) {
            float4 sc = *(const float4*)(scale + kk + a_k4);
            float4 sh = *(const float4*)(shift + kk + a_k4);
            v0.x = fmaxf(fmaf(v0.x, sc.x, sh.x), 0.f);
            v0.y = fmaxf(fmaf(v0.y, sc.y, sh.y), 0.f);
            v0.z = fmaxf(fmaf(v0.z, sc.z, sh.z), 0.f);
            v0.w = fmaxf(fmaf(v0.w, sc.w, sh.w), 0.f);
            v1.x = fmaxf(fmaf(v1.x, sc.x, sh.x), 0.f);
            v1.y = fmaxf(fmaf(v1.y, sc.y, sh.y), 0.f);
            v1.z = fmaxf(fmaf(v1.z, sc.z, sh.z), 0.f);
            v1.w = fmaxf(fmaf(v1.w, sc.w, sh.w), 0.f);
        }
    };
    auto loadB = [&](int kk, float4& v0, float4& v1) {
        v0 = *(const float4*)(Bbase + (size_t)kk * ncols);
        v1 = *(const float4*)(Bbase + (size_t)kk * ncols + BstepK);
    };
    auto storeAB = [&]() {
        uint4 u0 = make_uint4(f2tf32(pa0.x), f2tf32(pa0.y), f2tf32(pa0.z), f2tf32(pa0.w));
        uint4 u1 = make_uint4(f2tf32(pa1.x), f2tf32(pa1.y), f2tf32(pa1.z), f2tf32(pa1.w));
        *(uint4*)&As[a_row][a_k4]      = u0;
        *(uint4*)&As[a_row + 64][a_k4] = u1;
        uint4 w0 = make_uint4(f2tf32(pb0.x), f2tf32(pb0.y), f2tf32(pb0.z), f2tf32(pb0.w));
        uint4 w1 = make_uint4(f2tf32(pb1.x), f2tf32(pb1.y), f2tf32(pb1.z), f2tf32(pb1.w));
        *(uint4*)&Bs[b_k][b_c4]     = w0;
        *(uint4*)&Bs[b_k + 8][b_c4] = w1;
    };

    loadA(0, pa0, pa1);
    loadB(0, pb0, pb1);
    storeAB();
    __syncthreads();

    for (int kk = 0; kk < K; kk += 16) {
        const bool more = (kk + 16) < K;
        if (more) {
            loadA(kk + 16, pa0, pa1);
            loadB(kk + 16, pb0, pb1);
        }
#pragma unroll
        for (int ks = 0; ks < 2; ks++) {
            const int k0 = ks * 8;
            uint32_t af[4][4], bf[4][2];
#pragma unroll
            for (int mf = 0; mf < 4; mf++) {
                int m = wm * 64 + mf * 16 + g;
                af[mf][0] = As[m][k0 + tig];
                af[mf][1] = As[m + 8][k0 + tig];
                af[mf][2] = As[m][k0 + tig + 4];
                af[mf][3] = As[m + 8][k0 + tig + 4];
            }
#pragma unroll
            for (int nf = 0; nf < 4; nf++) {
                int n = wn * 32 + nf * 8 + g;
                bf[nf][0] = Bs[k0 + tig][n];
                bf[nf][1] = Bs[k0 + tig + 4][n];
            }
#pragma unroll
            for (int mf = 0; mf < 4; mf++)
#pragma unroll
                for (int nf = 0; nf < 4; nf++)
                    mma_tf32(acc[mf][nf], af[mf], bf[nf]);
        }
        if (more) {
            __syncthreads();
            storeAB();
            __syncthreads();
        }
    }

    // ---- epilogue ----
    float2 bb[4];
#pragma unroll
    for (int nf = 0; nf < 4; nf++)
        bb[nf] = *(const float2*)(bias + bcol + wn * 32 + nf * 8 + 2 * tig);

    if (STATS) {
        __syncthreads();
        if (tid < 128) { s_sum[tid] = 0.f; s_sq[tid] = 0.f; }
        __syncthreads();
    }

    float ls[4][2], lq[4][2];
#pragma unroll
    for (int nf = 0; nf < 4; nf++) {
        ls[nf][0] = 0.f; ls[nf][1] = 0.f;
        lq[nf][0] = 0.f; lq[nf][1] = 0.f;
    }

#pragma unroll
    for (int mf = 0; mf < 4; mf++) {
        int r0 = brow + wm * 64 + mf * 16 + g;
        int r1 = r0 + 8;
#pragma unroll
        for (int nf = 0; nf < 4; nf++) {
            int col = bcol + wn * 32 + nf * 8 + 2 * tig;
            float v0 = acc[mf][nf][0] + bb[nf].x;
            float v1 = acc[mf][nf][1] + bb[nf].y;
            float v2 = acc[mf][nf][2] + bb[nf].x;
            float v3 = acc[mf][nf][3] + bb[nf].y;
            if (r0 < Mstore) {
                float2 t = make_float2(v0, v1);
                *(float2*)(C + (size_t)r0 * ncols + col) = t;
            }
            if (r1 < Mstore) {
                float2 t = make_float2(v2, v3);
                *(float2*)(C + (size_t)r1 * ncols + col) = t;
            }
            if (STATS) {
                if (r0 < M) {
                    ls[nf][0] += v0; lq[nf][0] = fmaf(v0, v0, lq[nf][0]);
                    ls[nf][1] += v1; lq[nf][1] = fmaf(v1, v1, lq[nf][1]);
                }
                if (r1 < M) {
                    ls[nf][0] += v2; lq[nf][0] = fmaf(v2, v2, lq[nf][0]);
                    ls[nf][1] += v3; lq[nf][1] = fmaf(v3, v3, lq[nf][1]);
                }
            }
        }
    }

    if (STATS) {
#pragma unroll
        for (int nf = 0; nf < 4; nf++) {
            int scol = wn * 32 + nf * 8 + 2 * tig;
            atomicAdd(&s_sum[scol],     ls[nf][0]);
            atomicAdd(&s_sum[scol + 1], ls[nf][1]);
            atomicAdd(&s_sq[scol],      lq[nf][0]);
            atomicAdd(&s_sq[scol + 1],  lq[nf][1]);
        }
        __syncthreads();
        if (tid < 128) {
            atomicAdd(&g_sum[bcol + tid], s_sum[tid]);
            atomicAdd(&g_sq[bcol + tid],  s_sq[tid]);
        }
    }
}

__global__ __launch_bounds__(256)
void gemm1_kernel(const float* __restrict__ B, const float* __restrict__ bias, int M) {
    mma_gemm<false, true>(g_hin, B, g_h1, bias, M, MPAD, D_IN, D_HID,
                          nullptr, nullptr);
}

__global__ __launch_bounds__(256)
void gemm2_kernel(const float* __restrict__ B, const float* __restrict__ bias,
                  float* __restrict__ C, int M) {
    mma_gemm<true, false>(g_h1, B, C, bias, M, M, D_HID, D_OUT,
                          g_scale, g_shift);
}

// ---------------- BN finalize: scale/shift from sums ------------------------
__global__ void finalize_kernel(const float* __restrict__ gamma,
                                const float* __restrict__ beta, int M) {
    int c = blockIdx.x * blockDim.x + threadIdx.x;
    if (c < D_HID) {
        float inv = 1.0f / (float)M;
        float m   = g_sum[c] * inv;
        float var = fmaxf(g_sq[c] * inv - m * m, 0.f);
        float r   = rsqrtf(var + 1e-5f);
        float sc  = r * gamma[c];
        g_scale[c] = sc;
        g_shift[c] = fmaf(-m, sc, beta[c]);
    }
}

// ---------------- launch -----------------------------------------------------
extern "C" void kernel_launch(void* const* d_in, const int* in_sizes, int n_in,
                              void* d_out, int out_size) {
    const float* x     = (const float*)d_in[0];
    const int*   esrc  = (const int*)  d_in[1];
    const int*   edst  = (const int*)  d_in[2];
    const float* ew    = (const float*)d_in[3];
    const float* w1    = (const float*)d_in[4];
    const float* b1    = (const float*)d_in[5];
    const float* gamma = (const float*)d_in[6];
    const float* beta  = (const float*)d_in[7];
    const float* w2    = (const float*)d_in[8];
    const float* b2    = (const float*)d_in[9];
    float* out = (float*)d_out;

    int N = in_sizes[0] / D_IN;
    int E = in_sizes[1];
    if (N > NMAX) N = NMAX;
    if (E > EMAX) E = EMAX;

    int n1 = N + 1;
    int nb = (n1 + 1023) / 1024;

    // init
    zero_kernel<<<(n1 + 1023) / 1024, 1024>>>(n1);
    // CSR build
    hist_kernel<<<(E + 255) / 256, 256>>>(edst, E);
    scan1_kernel<<<nb, 1024>>>(n1);
    scan2_kernel<<<1, 128>>>(nb);
    scan3_kernel<<<nb, 1024>>>(n1, N);
    scatter_kernel<<<(E + 255) / 256, 256>>>(esrc, edst, ew, E);
    // SpMM + (1+eps)x
    {
        int warps = MPAD;
        int blocks = (warps * 32 + 255) / 256;
        spmm_kernel<<<blocks, 256>>>(x, N, MPAD);
    }
    // GEMM1 (+bias, +BN column stats), TF32 tensor cores
    {
        dim3 grid(D_HID / 128, MPAD / 128);
        gemm1_kernel<<<grid, 256>>>(w1, b1, N);
    }
    // BN scale/shift
    finalize_kernel<<<1, 512>>>(gamma, beta, N);
    // GEMM2 with fused BN+ReLU on A (+bias), TF32, store to d_out
    {
        dim3 grid(D_OUT / 128, MPAD / 128);
        gemm2_kernel<<<grid, 256>>>(w2, b2, out, N);
    }
}